// round 15
// baseline (speedup 1.0000x reference)
#include <cuda_runtime.h>
#include <math.h>

// ---------------- problem constants ----------------
#define Bn    2
#define Cin   32
#define Cout  64
#define Dd    48
#define Hh    48
#define Ww    48
#define HWc   (Hh*Ww)          // 2304
#define Ss    (Dd*Hh*Ww)       // 110592
#define NPTS  (Bn*Ss)          // 221184
#define NBLK  (NPTS/128)       // 1728 point-kernel blocks
#define BPB   (Ss/128)         // 864 blocks per batch
#define EPSf  1e-5f

// ---------------- scratch (no runtime allocation) ----------------
__device__ float g_off_raw[Bn*6*Ss];       // raw offset-conv, channels 3..8 ~5.3MB
__device__ float g_conv_out[Bn*Cout*Ss];   // pre-GN conv output ~56.6MB
__device__ float g_bn_part[12*NBLK];
__device__ float g_bn_red[12];
__device__ float g_bn_scale[6];
__device__ float g_bn_shift[6];
__device__ float g_gn_part[64*BPB];        // (b*32 + slot)*BPB + blk
__device__ float g_gn_red[64];
__device__ float g_gn_a[Bn*Cout];
__device__ float g_gn_b[Bn*Cout];

// ---------------- packed f32x2 helpers ----------------
__device__ __forceinline__ unsigned long long pack2(float x, float y) {
    unsigned long long r;
    asm("mov.b64 %0, {%1, %2};" : "=l"(r) : "f"(x), "f"(y));
    return r;
}
__device__ __forceinline__ float2 unpack2(unsigned long long v) {
    float2 r;
    asm("mov.b64 {%0, %1}, %2;" : "=f"(r.x), "=f"(r.y) : "l"(v));
    return r;
}
__device__ __forceinline__ void ffma2u(unsigned long long& d,
                                       unsigned long long a,
                                       unsigned long long b) {
    asm("fma.rn.f32x2 %0, %1, %2, %0;" : "+l"(d) : "l"(a), "l"(b));
}

// ---------------- kernel 1: offset conv (3x3x3, SAME), 6 live channels ----------------
// Channel-major x; lanes along w -> all LDG coalesced. f32x2 lanes = channel pairs.
__global__ void __launch_bounds__(128) k_offconv(const float* __restrict__ x,
                                                 const float* __restrict__ ow,
                                                 const float* __restrict__ ob) {
    __shared__ __align__(16) unsigned long long s_w[27*16*6];  // [(tap*16+c2)*6 + j]
    __shared__ float s_bias[6];
    __shared__ float s_warp[4][12];

    int tid = threadIdx.x;
    for (int idx = tid; idx < 27*16*6; idx += 128) {
        int j   = idx % 6;
        int c2  = (idx / 6) % 16;
        int tap = idx / 96;
        s_w[idx] = pack2(ow[(3+j)*(Cin*27) + (2*c2  )*27 + tap],
                         ow[(3+j)*(Cin*27) + (2*c2+1)*27 + tap]);
    }
    if (tid < 6) s_bias[tid] = ob[3+tid];
    __syncthreads();

    int p  = blockIdx.x * 128 + tid;
    int b  = p / Ss;
    int rr = p - b*Ss;
    int d  = rr / HWc;
    int hw = rr - d*HWc;
    int h  = hw / Ww;
    int w  = hw - h*Ww;

    unsigned long long acc[6] = {0ULL,0ULL,0ULL,0ULL,0ULL,0ULL};
    const float* xb = x + b*(Cin*Ss);

#pragma unroll 1
    for (int kd = 0; kd < 3; kd++) {
        int zz = d + kd - 1; if ((unsigned)zz >= Dd) continue;
#pragma unroll 1
        for (int kh = 0; kh < 3; kh++) {
            int yy = h + kh - 1; if ((unsigned)yy >= Hh) continue;
#pragma unroll 1
            for (int kw = 0; kw < 3; kw++) {
                int xx = w + kw - 1; if ((unsigned)xx >= Ww) continue;
                int tap = (kd*3 + kh)*3 + kw;
                const float* xp = xb + (zz*HWc + yy*Ww + xx);
                const ulonglong2* wq = (const ulonglong2*)&s_w[tap*96];
#pragma unroll
                for (int c2 = 0; c2 < 16; c2++) {
                    float v0 = xp[0];
                    float v1 = xp[Ss];
                    xp += 2*Ss;
                    unsigned long long sv = pack2(v0, v1);
                    ulonglong2 a0 = wq[0], a1 = wq[1], a2 = wq[2];
                    wq += 3;
                    ffma2u(acc[0], sv, a0.x); ffma2u(acc[1], sv, a0.y);
                    ffma2u(acc[2], sv, a1.x); ffma2u(acc[3], sv, a1.y);
                    ffma2u(acc[4], sv, a2.x); ffma2u(acc[5], sv, a2.y);
                }
            }
        }
    }

    float red[12];
#pragma unroll
    for (int j = 0; j < 6; j++) {
        float2 a = unpack2(acc[j]);
        float v = a.x + a.y + s_bias[j];   // even-channel + odd-channel partials
        g_off_raw[(b*6 + j)*Ss + rr] = v;
        red[j]     = v;
        red[6 + j] = v * v;
    }

    int lane = tid & 31, wid = tid >> 5;
#pragma unroll
    for (int r = 0; r < 12; r++) {
        float t = red[r];
        t += __shfl_down_sync(0xffffffffu, t, 16);
        t += __shfl_down_sync(0xffffffffu, t, 8);
        t += __shfl_down_sync(0xffffffffu, t, 4);
        t += __shfl_down_sync(0xffffffffu, t, 2);
        t += __shfl_down_sync(0xffffffffu, t, 1);
        if (lane == 0) s_warp[wid][r] = t;
    }
    __syncthreads();
    if (tid < 12)
        g_bn_part[tid*NBLK + blockIdx.x] =
            s_warp[0][tid] + s_warp[1][tid] + s_warp[2][tid] + s_warp[3][tid];
}

// ---------------- kernel 2a: deterministic BN partial reduce ----------------
__global__ void k_bnred() {
    __shared__ float sh[256];
    int s = blockIdx.x;                   // 0..11
    float a = 0.f;
    for (int i = threadIdx.x; i < NBLK; i += 256)
        a += g_bn_part[s*NBLK + i];
    sh[threadIdx.x] = a;
    __syncthreads();
    for (int st = 128; st; st >>= 1) {
        if (threadIdx.x < st) sh[threadIdx.x] += sh[threadIdx.x + st];
        __syncthreads();
    }
    if (threadIdx.x == 0) g_bn_red[s] = sh[0];
}

// ---------------- kernel 2b: BN finalize ----------------
__global__ void k_bnfin(const float* __restrict__ bng, const float* __restrict__ bnb) {
    int j = threadIdx.x;
    if (j < 6) {
        float n    = (float)NPTS;
        float mean = g_bn_red[j] / n;
        float var  = g_bn_red[6 + j] / n - mean*mean;
        float sc   = bng[3 + j] * rsqrtf(fmaxf(var, 0.f) + EPSf);
        g_bn_scale[j] = sc;
        g_bn_shift[j] = bnb[3 + j] - mean * sc;
    }
}

// ---------------- kernel 3: fused BN+tanh+offsets+bilinear sample+1x1xK conv ----------------
// 256 threads / 128 points: thread pair splits the 64 output channels.
// half = tid>>7 owns channels [half*32, half*32+32) as 16 f32x2 accumulators.
__global__ void __launch_bounds__(256, 3) k_sampconv(const float* __restrict__ x,
                                                     const float* __restrict__ cw,
                                                     const float* __restrict__ cb) {
    __shared__ __align__(16) unsigned long long s_cw[3*32*32];  // [(k*32+c)*32 + j]
    __shared__ unsigned long long s_cb[32];
    __shared__ float s_warp[8][16];

    int tid = threadIdx.x;
    for (int idx = tid; idx < 3072; idx += 256) {
        int j = idx & 31;
        int c = (idx >> 5) & 31;
        int k = idx >> 10;
        s_cw[idx] = pack2(cw[(2*j  )*96 + c*3 + k],
                          cw[(2*j+1)*96 + c*3 + k]);
    }
    if (tid < 32) s_cb[tid] = pack2(cb[2*tid], cb[2*tid+1]);
    __syncthreads();

    int half = tid >> 7;                 // 0 or 1: which 32-channel half
    int pp   = tid & 127;                // point within block
    int b    = blockIdx.x / BPB;
    int blkb = blockIdx.x - b*BPB;
    int rr   = blkb * 128 + pp;
    int d  = rr / HWc;
    int hw = rr - d*HWc;
    int h  = hw / Ww;
    int w  = hw - h*Ww;

    // BN + tanh on the 6 live offset channels (twin threads: L1 hit)
    float off[6];
#pragma unroll
    for (int j = 0; j < 6; j++) {
        float raw = g_off_raw[(b*6 + j)*Ss + rr];
        off[j] = tanhf(fmaf(raw, g_bn_scale[j], g_bn_shift[j]));
    }
    // K=3 cumulative offsets: center k=1 is zero, edges are single taps
    float cy[3] = { off[0], 0.f, off[2] };
    float cx[3] = { off[3], 0.f, off[5] };

    unsigned long long acc[16];
#pragma unroll
    for (int j = 0; j < 16; j++) acc[j] = s_cb[half*16 + j];

    const float* xb = x + b*(Cin*Ss);

#pragma unroll 1
    for (int k = 0; k < 3; k++) {
        int z = d + k - 1;
        z = max(0, min(z, Dd - 1));                         // integer z -> bilinear
        float yf = fminf(fmaxf((float)h + cy[k], 0.f), (float)(Hh - 1));
        float xf = fminf(fmaxf((float)w + cx[k], 0.f), (float)(Ww - 1));
        float y0f = floorf(yf), x0f = floorf(xf);
        float wy = yf - y0f, wx = xf - x0f;
        int y0 = (int)y0f, x0 = (int)x0f;
        int y1 = min(y0 + 1, Hh - 1), x1 = min(x0 + 1, Ww - 1);
        float w00 = (1.f - wy) * (1.f - wx);
        float w01 = (1.f - wy) * wx;
        float w10 = wy * (1.f - wx);
        float w11 = wy * wx;

        const float* q00 = xb + (z*HWc + y0*Ww + x0);
        const float* q01 = xb + (z*HWc + y0*Ww + x1);
        const float* q10 = xb + (z*HWc + y1*Ww + x0);
        const float* q11 = xb + (z*HWc + y1*Ww + x1);
        const ulonglong2* wk = (const ulonglong2*)&s_cw[(k*32)*32 + half*16];

#pragma unroll 4
        for (int c = 0; c < 32; c++) {
            float a0 = q00[0], a1 = q01[0], a2 = q10[0], a3 = q11[0];
            q00 += Ss; q01 += Ss; q10 += Ss; q11 += Ss;
            float s = fmaf(w00, a0, fmaf(w01, a1, fmaf(w10, a2, w11 * a3)));
            unsigned long long sv = pack2(s, s);
#pragma unroll
            for (int i = 0; i < 8; i++) {
                ulonglong2 ww = wk[i];
                ffma2u(acc[2*i  ], sv, ww.x);
                ffma2u(acc[2*i+1], sv, ww.y);
            }
            wk += 16;
        }
    }

    // write conv output (coalesced per channel) + GN partials
#pragma unroll
    for (int j = 0; j < 16; j++) {
        float2 v = unpack2(acc[j]);
        int ch = half*32 + 2*j;
        g_conv_out[(b*Cout + ch    )*Ss + rr] = v.x;
        g_conv_out[(b*Cout + ch + 1)*Ss + rr] = v.y;
    }

    // GN partials: group g = 4 channels = pairs {2lg, 2lg+1} locally.
    // Warp = 32 points of one half -> 8 local groups (global g = half*8 + lg).
    int lane = tid & 31, wid = tid >> 5;   // wid 0..7; wid<4 => half 0
#pragma unroll
    for (int lg = 0; lg < 8; lg++) {
        float2 v0 = unpack2(acc[2*lg]);
        float2 v1 = unpack2(acc[2*lg + 1]);
        float s = v0.x + v0.y + v1.x + v1.y;
        float q = v0.x*v0.x + v0.y*v0.y + v1.x*v1.x + v1.y*v1.y;
        s += __shfl_down_sync(0xffffffffu, s, 16);
        q += __shfl_down_sync(0xffffffffu, q, 16);
        s += __shfl_down_sync(0xffffffffu, s, 8);
        q += __shfl_down_sync(0xffffffffu, q, 8);
        s += __shfl_down_sync(0xffffffffu, s, 4);
        q += __shfl_down_sync(0xffffffffu, q, 4);
        s += __shfl_down_sync(0xffffffffu, s, 2);
        q += __shfl_down_sync(0xffffffffu, q, 2);
        s += __shfl_down_sync(0xffffffffu, s, 1);
        q += __shfl_down_sync(0xffffffffu, q, 1);
        if (lane == 0) { s_warp[wid][lg] = s; s_warp[wid][8 + lg] = q; }
    }
    __syncthreads();
    if (tid < 32) {
        // slot tid: tid<16 -> sum of group tid ; tid>=16 -> sumsq of group tid-16
        int g   = tid & 15;
        int isq = tid >> 4;
        int hh  = g >> 3;         // half that owns this group
        int col = isq*8 + (g & 7);
        float v = s_warp[hh*4+0][col] + s_warp[hh*4+1][col]
                + s_warp[hh*4+2][col] + s_warp[hh*4+3][col];
        g_gn_part[(b*32 + tid)*BPB + blkb] = v;
    }
}

// ---------------- kernel 4a: deterministic GN partial reduce ----------------
__global__ void k_gnred() {
    __shared__ float sh[256];
    int s = blockIdx.x;                   // 0..63 = b*32 + slot
    float a = 0.f;
    for (int i = threadIdx.x; i < BPB; i += 256)
        a += g_gn_part[s*BPB + i];
    sh[threadIdx.x] = a;
    __syncthreads();
    for (int st = 128; st; st >>= 1) {
        if (threadIdx.x < st) sh[threadIdx.x] += sh[threadIdx.x + st];
        __syncthreads();
    }
    if (threadIdx.x == 0) g_gn_red[s] = sh[0];
}

// ---------------- kernel 4b: GN finalize (per (b,channel) affine) ----------------
__global__ void k_gnfin(const float* __restrict__ gng, const float* __restrict__ gnb) {
    int t = threadIdx.x;
    if (t < Bn*Cout) {
        int b = t >> 6, o = t & 63, g = o >> 2;
        float n    = 4.f * (float)Ss;
        float mean = g_gn_red[b*32 + g] / n;
        float var  = g_gn_red[b*32 + 16 + g] / n - mean*mean;
        float a    = gng[o] * rsqrtf(fmaxf(var, 0.f) + EPSf);
        g_gn_a[t] = a;
        g_gn_b[t] = gnb[o] - mean * a;
    }
}

// ---------------- kernel 5: GN apply + ReLU ----------------
__global__ void k_gnapply(float* __restrict__ out) {
    int i = blockIdx.x * 256 + threadIdx.x;
    if (i >= (Bn*Cout*Ss) / 4) return;
    int cidx = i / (Ss / 4);
    float a = g_gn_a[cidx], bsh = g_gn_b[cidx];
    float4 v = reinterpret_cast<const float4*>(g_conv_out)[i];
    float4 r;
    r.x = fmaxf(fmaf(v.x, a, bsh), 0.f);
    r.y = fmaxf(fmaf(v.y, a, bsh), 0.f);
    r.z = fmaxf(fmaf(v.z, a, bsh), 0.f);
    r.w = fmaxf(fmaf(v.w, a, bsh), 0.f);
    reinterpret_cast<float4*>(out)[i] = r;
}

// ---------------- launch ----------------
extern "C" void kernel_launch(void* const* d_in, const int* in_sizes, int n_in,
                              void* d_out, int out_size) {
    const float* x   = (const float*)d_in[0];
    const float* ow  = (const float*)d_in[1];
    const float* ob  = (const float*)d_in[2];
    const float* bng = (const float*)d_in[3];
    const float* bnb = (const float*)d_in[4];
    const float* cw  = (const float*)d_in[5];
    const float* cb  = (const float*)d_in[6];
    const float* gng = (const float*)d_in[7];
    const float* gnb = (const float*)d_in[8];

    k_offconv<<<NBLK, 128>>>(x, ow, ob);
    k_bnred<<<12, 256>>>();
    k_bnfin<<<1, 32>>>(bng, bnb);
    k_sampconv<<<NBLK, 256>>>(x, cw, cb);
    k_gnred<<<64, 256>>>();
    k_gnfin<<<1, 128>>>(gng, gnb);
    k_gnapply<<<(Bn*Cout*Ss/4 + 255)/256, 256>>>((float*)d_out);
}

// round 16
// speedup vs baseline: 1.4347x; 1.4347x over previous
#include <cuda_runtime.h>
#include <math.h>

// ---------------- problem constants ----------------
#define Bn    2
#define Cin   32
#define Cout  64
#define Dd    48
#define Hh    48
#define Ww    48
#define HWc   (Hh*Ww)          // 2304
#define Ss    (Dd*Hh*Ww)       // 110592
#define NPTS  (Bn*Ss)          // 221184
#define BPB   (Ss/128)         // 864 sampconv blocks per batch
#define NSB   (Bn*BPB)         // 1728 sampconv blocks
#define NOB   (Bn*Dd*8)        // 768 offconv blocks (6 h-rows each)
#define EPSf  1e-5f

// ---------------- scratch (no runtime allocation) ----------------
__device__ float g_off_raw[Bn*6*Ss];       // raw offset-conv, channels 3..8
__device__ float g_conv_out[Bn*Cout*Ss];   // pre-GN conv output
__device__ __align__(16) unsigned long long g_w2[96*32];  // prepacked conv weights [kc][j]
__device__ float g_bn_part[12*NOB];
__device__ float g_bn_red[12];
__device__ float g_bn_scale[6];
__device__ float g_bn_shift[6];
__device__ float g_gn_part[64*BPB];        // (b*32 + slot)*BPB + blk
__device__ float g_gn_red[64];
__device__ float g_gn_a[Bn*Cout];
__device__ float g_gn_b[Bn*Cout];

// ---------------- packed f32x2 helpers ----------------
__device__ __forceinline__ unsigned long long pack2(float x, float y) {
    unsigned long long r;
    asm("mov.b64 %0, {%1, %2};" : "=l"(r) : "f"(x), "f"(y));
    return r;
}
__device__ __forceinline__ float2 unpack2(unsigned long long v) {
    float2 r;
    asm("mov.b64 {%0, %1}, %2;" : "=f"(r.x), "=f"(r.y) : "l"(v));
    return r;
}
__device__ __forceinline__ void ffma2u(unsigned long long& d,
                                       unsigned long long a,
                                       unsigned long long b) {
    asm("fma.rn.f32x2 %0, %1, %2, %0;" : "+l"(d) : "l"(a), "l"(b));
}

// ---------------- kernel 0: prepack 1x1xK conv weights ----------------
// g_w2[kc*32 + j] = pack(cw[2j][c][k], cw[2j+1][c][k]) with kc = k*32 + c
__global__ void k_prepw(const float* __restrict__ cw) {
    int idx = blockIdx.x * 256 + threadIdx.x;
    if (idx < 96*32) {
        int j  = idx & 31;
        int kc = idx >> 5;
        int c  = kc & 31;
        int k  = kc >> 5;
        g_w2[idx] = pack2(cw[(2*j  )*96 + c*3 + k],
                          cw[(2*j+1)*96 + c*3 + k]);
    }
}

// ---------------- kernel 1: offset conv (3x3x3, SAME), 6 live channels ----------------
// 96 threads; thread owns 3 h-consecutive points. x 5x3 block reused over taps,
// weights reused over the 3 points. f32x2 lanes = channel pairs.
__global__ void __launch_bounds__(96, 5) k_offconv(const float* __restrict__ x,
                                                   const float* __restrict__ ow,
                                                   const float* __restrict__ ob) {
    __shared__ __align__(16) unsigned long long s_w[27*96];  // [tap][c2*6 + j]
    __shared__ float s_bias[6];
    __shared__ float s_warp[3][12];

    int t = threadIdx.x;
    for (int idx = t; idx < 27*96; idx += 96) {
        int j   = idx % 6;
        int c2  = (idx / 6) % 16;
        int tap = idx / 96;
        s_w[idx] = pack2(ow[(3+j)*(Cin*27) + (2*c2  )*27 + tap],
                         ow[(3+j)*(Cin*27) + (2*c2+1)*27 + tap]);
    }
    if (t < 6) s_bias[t] = ob[3+t];
    __syncthreads();

    int w  = t % 48;
    int ht = t / 48;                    // 0 or 1
    int blk = blockIdx.x;
    int h8 = blk & 7;
    int d  = (blk >> 3) % Dd;
    int b  = blk / (8*Dd);
    int h0 = h8*6 + ht*3;               // base h of this thread's 3 points

    unsigned long long acc[3][6];
#pragma unroll
    for (int ph = 0; ph < 3; ph++)
#pragma unroll
        for (int j = 0; j < 6; j++) acc[ph][j] = 0ULL;

    const float* xb = x + b*(Cin*Ss);

#pragma unroll 1
    for (int kd = 0; kd < 3; kd++) {
        int zz = d + kd - 1;
        if ((unsigned)zz >= Dd) continue;
        const float* xz = xb + zz*HWc;
#pragma unroll 1
        for (int c2 = 0; c2 < 16; c2++) {
            const float* xc = xz + (2*c2)*Ss;
            // load 5 rows x 3 cols, 2 channels packed
            unsigned long long xv[5][3];
#pragma unroll
            for (int r = 0; r < 5; r++) {
                int yy = h0 - 1 + r;
                bool vr = (unsigned)yy < Hh;
#pragma unroll
                for (int col = 0; col < 3; col++) {
                    int xx = w - 1 + col;
                    float v0 = 0.f, v1 = 0.f;
                    if (vr && (unsigned)xx < Ww) {
                        int o = yy*Ww + xx;
                        v0 = xc[o];
                        v1 = xc[o + Ss];
                    }
                    xv[r][col] = pack2(v0, v1);
                }
            }
            const unsigned long long* wt = &s_w[(kd*9)*96 + c2*6];
#pragma unroll
            for (int kh = 0; kh < 3; kh++) {
#pragma unroll
                for (int kw = 0; kw < 3; kw++) {
                    const ulonglong2* wq = (const ulonglong2*)(wt + (kh*3 + kw)*96);
                    ulonglong2 a0 = wq[0], a1 = wq[1], a2 = wq[2];
#pragma unroll
                    for (int ph = 0; ph < 3; ph++) {
                        unsigned long long sv = xv[kh + ph][kw];
                        ffma2u(acc[ph][0], sv, a0.x); ffma2u(acc[ph][1], sv, a0.y);
                        ffma2u(acc[ph][2], sv, a1.x); ffma2u(acc[ph][3], sv, a1.y);
                        ffma2u(acc[ph][4], sv, a2.x); ffma2u(acc[ph][5], sv, a2.y);
                    }
                }
            }
        }
    }

    float red[12];
#pragma unroll
    for (int r = 0; r < 12; r++) red[r] = 0.f;
#pragma unroll
    for (int ph = 0; ph < 3; ph++) {
        int rr = d*HWc + (h0 + ph)*Ww + w;
#pragma unroll
        for (int j = 0; j < 6; j++) {
            float2 a = unpack2(acc[ph][j]);
            float v = a.x + a.y + s_bias[j];   // even + odd channel partials
            g_off_raw[(b*6 + j)*Ss + rr] = v;
            red[j]     += v;
            red[6 + j] += v*v;
        }
    }

    int lane = t & 31, wid = t >> 5;   // 3 warps
#pragma unroll
    for (int r = 0; r < 12; r++) {
        float v = red[r];
        v += __shfl_down_sync(0xffffffffu, v, 16);
        v += __shfl_down_sync(0xffffffffu, v, 8);
        v += __shfl_down_sync(0xffffffffu, v, 4);
        v += __shfl_down_sync(0xffffffffu, v, 2);
        v += __shfl_down_sync(0xffffffffu, v, 1);
        if (lane == 0) s_warp[wid][r] = v;
    }
    __syncthreads();
    if (t < 12)
        g_bn_part[t*NOB + blockIdx.x] =
            s_warp[0][t] + s_warp[1][t] + s_warp[2][t];
}

// ---------------- kernel 2a: deterministic BN partial reduce ----------------
__global__ void k_bnred() {
    __shared__ float sh[256];
    int s = blockIdx.x;                   // 0..11
    float a = 0.f;
    for (int i = threadIdx.x; i < NOB; i += 256)
        a += g_bn_part[s*NOB + i];
    sh[threadIdx.x] = a;
    __syncthreads();
    for (int st = 128; st; st >>= 1) {
        if (threadIdx.x < st) sh[threadIdx.x] += sh[threadIdx.x + st];
        __syncthreads();
    }
    if (threadIdx.x == 0) g_bn_red[s] = sh[0];
}

// ---------------- kernel 2b: BN finalize ----------------
__global__ void k_bnfin(const float* __restrict__ bng, const float* __restrict__ bnb) {
    int j = threadIdx.x;
    if (j < 6) {
        float n    = (float)NPTS;
        float mean = g_bn_red[j] / n;
        float var  = g_bn_red[6 + j] / n - mean*mean;
        float sc   = bng[3 + j] * rsqrtf(fmaxf(var, 0.f) + EPSf);
        g_bn_scale[j] = sc;
        g_bn_shift[j] = bnb[3 + j] - mean * sc;
    }
}

// ---------------- kernel 3: fused sample + 1x1xK conv, two-phase ----------------
// Phase 1: 256 threads compute each of the 96 (tap,channel) samples ONCE for
//          128 points into smem (kc-half split across tid>>7).
// Phase 2: thread = (quarter q = tid>>6) x (pg = tid&63) owns 2 points x 16 ch.
//          Weights via uniform LDG.128 from g_w2 (L1-resident).
__global__ void __launch_bounds__(256, 3) k_sampconv(const float* __restrict__ x,
                                                     const float* __restrict__ cb) {
    __shared__ float s_s[96*128];   // 48KB sampled values [kc][point]

    int t = threadIdx.x;
    int b = blockIdx.x / BPB;
    int blkb = blockIdx.x - b*BPB;

    // ---- phase 1: gather + bilinear ----
    {
        int p = t & 127;
        int khalf = t >> 7;
        int rr = blkb*128 + p;
        int d  = rr / HWc;
        int hw = rr - d*HWc;
        int h  = hw / Ww;
        int w  = hw - h*Ww;

        float off[6];
#pragma unroll
        for (int j = 0; j < 6; j++) {
            float raw = g_off_raw[(b*6 + j)*Ss + rr];
            off[j] = tanhf(fmaf(raw, g_bn_scale[j], g_bn_shift[j]));
        }
        float cy[3] = { off[0], 0.f, off[2] };
        float cx[3] = { off[3], 0.f, off[5] };

        const float* xb = x + b*(Cin*Ss);

#pragma unroll 1
        for (int seg = 0; seg < 2; seg++) {
            int k = khalf + seg;          // half0: k=0,1 ; half1: k=1,2
            int cbeg = 0, cend = 32;
            if (k == 1) { if (khalf == 0) cend = 16; else cbeg = 16; }

            int z = d + k - 1;
            z = max(0, min(z, Dd - 1));
            float yf = fminf(fmaxf((float)h + cy[k], 0.f), (float)(Hh - 1));
            float xf = fminf(fmaxf((float)w + cx[k], 0.f), (float)(Ww - 1));
            float y0f = floorf(yf), x0f = floorf(xf);
            float wy = yf - y0f, wx = xf - x0f;
            int y0 = (int)y0f, x0 = (int)x0f;
            int y1 = min(y0 + 1, Hh - 1), x1 = min(x0 + 1, Ww - 1);
            float w00 = (1.f - wy) * (1.f - wx);
            float w01 = (1.f - wy) * wx;
            float w10 = wy * (1.f - wx);
            float w11 = wy * wx;

            const float* q00 = xb + cbeg*Ss + (z*HWc + y0*Ww + x0);
            const float* q01 = xb + cbeg*Ss + (z*HWc + y0*Ww + x1);
            const float* q10 = xb + cbeg*Ss + (z*HWc + y1*Ww + x0);
            const float* q11 = xb + cbeg*Ss + (z*HWc + y1*Ww + x1);
            float* sd = &s_s[(k*32 + cbeg)*128 + p];

#pragma unroll 4
            for (int c = cbeg; c < cend; c++) {
                float a0 = q00[0], a1 = q01[0], a2 = q10[0], a3 = q11[0];
                q00 += Ss; q01 += Ss; q10 += Ss; q11 += Ss;
                *sd = fmaf(w00, a0, fmaf(w01, a1, fmaf(w10, a2, w11 * a3)));
                sd += 128;
            }
        }
    }
    __syncthreads();

    // ---- phase 2: matvec, 2 points x 16 channels per thread ----
    int q  = t >> 6;                     // channel quarter (warps uniform in q)
    int tq = t & 63;                     // point group: points {tq, tq+64}

    unsigned long long acc0[8], acc1[8];
#pragma unroll
    for (int j = 0; j < 8; j++) {
        int ch = q*16 + 2*j;
        unsigned long long bv = pack2(cb[ch], cb[ch+1]);
        acc0[j] = bv; acc1[j] = bv;
    }

    const float* srow = &s_s[tq];
    const ulonglong2* wbase = (const ulonglong2*)g_w2 + q*4;

#pragma unroll 2
    for (int kc = 0; kc < 96; kc++) {
        float s0 = srow[kc*128];
        float s1 = srow[kc*128 + 64];
        unsigned long long sv0 = pack2(s0, s0);
        unsigned long long sv1 = pack2(s1, s1);
        const ulonglong2* wq = wbase + kc*16;
        ulonglong2 w0 = wq[0], w1 = wq[1], w2 = wq[2], w3 = wq[3];
        ffma2u(acc0[0], sv0, w0.x); ffma2u(acc0[1], sv0, w0.y);
        ffma2u(acc0[2], sv0, w1.x); ffma2u(acc0[3], sv0, w1.y);
        ffma2u(acc0[4], sv0, w2.x); ffma2u(acc0[5], sv0, w2.y);
        ffma2u(acc0[6], sv0, w3.x); ffma2u(acc0[7], sv0, w3.y);
        ffma2u(acc1[0], sv1, w0.x); ffma2u(acc1[1], sv1, w0.y);
        ffma2u(acc1[2], sv1, w1.x); ffma2u(acc1[3], sv1, w1.y);
        ffma2u(acc1[4], sv1, w2.x); ffma2u(acc1[5], sv1, w2.y);
        ffma2u(acc1[6], sv1, w3.x); ffma2u(acc1[7], sv1, w3.y);
    }

    // stores + GN local sums
    int rr0 = blkb*128 + tq;
    int rr1 = rr0 + 64;
    float lg_s[4] = {0.f,0.f,0.f,0.f};
    float lg_q[4] = {0.f,0.f,0.f,0.f};
#pragma unroll
    for (int j = 0; j < 8; j++) {
        float2 v0 = unpack2(acc0[j]);
        float2 v1 = unpack2(acc1[j]);
        int ch = q*16 + 2*j;
        g_conv_out[(b*Cout + ch    )*Ss + rr0] = v0.x;
        g_conv_out[(b*Cout + ch + 1)*Ss + rr0] = v0.y;
        g_conv_out[(b*Cout + ch    )*Ss + rr1] = v1.x;
        g_conv_out[(b*Cout + ch + 1)*Ss + rr1] = v1.y;
        int lg = j >> 1;
        lg_s[lg] += v0.x + v0.y + v1.x + v1.y;
        lg_q[lg] += v0.x*v0.x + v0.y*v0.y + v1.x*v1.x + v1.y*v1.y;
    }

    int lane = t & 31, wid = t >> 5;     // 8 warps; quarter = wid>>1
    __syncthreads();                     // all s_s reads done -> reuse as s_red
    float* s_red = s_s;
#pragma unroll
    for (int lg = 0; lg < 4; lg++) {
        float s = lg_s[lg], qq = lg_q[lg];
        s += __shfl_down_sync(0xffffffffu, s, 16);
        qq += __shfl_down_sync(0xffffffffu, qq, 16);
        s += __shfl_down_sync(0xffffffffu, s, 8);
        qq += __shfl_down_sync(0xffffffffu, qq, 8);
        s += __shfl_down_sync(0xffffffffu, s, 4);
        qq += __shfl_down_sync(0xffffffffu, qq, 4);
        s += __shfl_down_sync(0xffffffffu, s, 2);
        qq += __shfl_down_sync(0xffffffffu, qq, 2);
        s += __shfl_down_sync(0xffffffffu, s, 1);
        qq += __shfl_down_sync(0xffffffffu, qq, 1);
        if (lane == 0) { s_red[wid*8 + lg] = s; s_red[wid*8 + 4 + lg] = qq; }
    }
    __syncthreads();
    if (t < 32) {
        // slot t: t<16 -> sum of group t ; t>=16 -> sumsq of group t-16
        int isq = t >> 4, g = t & 15, qq = g >> 2, lg = g & 3;
        float v = s_red[(2*qq  )*8 + isq*4 + lg]
                + s_red[(2*qq+1)*8 + isq*4 + lg];
        g_gn_part[(b*32 + t)*BPB + blkb] = v;
    }
}

// ---------------- kernel 4a: deterministic GN partial reduce ----------------
__global__ void k_gnred() {
    __shared__ float sh[256];
    int s = blockIdx.x;                   // 0..63 = b*32 + slot
    float a = 0.f;
    for (int i = threadIdx.x; i < BPB; i += 256)
        a += g_gn_part[s*BPB + i];
    sh[threadIdx.x] = a;
    __syncthreads();
    for (int st = 128; st; st >>= 1) {
        if (threadIdx.x < st) sh[threadIdx.x] += sh[threadIdx.x + st];
        __syncthreads();
    }
    if (threadIdx.x == 0) g_gn_red[s] = sh[0];
}

// ---------------- kernel 4b: GN finalize (per (b,channel) affine) ----------------
__global__ void k_gnfin(const float* __restrict__ gng, const float* __restrict__ gnb) {
    int t = threadIdx.x;
    if (t < Bn*Cout) {
        int b = t >> 6, o = t & 63, g = o >> 2;
        float n    = 4.f * (float)Ss;
        float mean = g_gn_red[b*32 + g] / n;
        float var  = g_gn_red[b*32 + 16 + g] / n - mean*mean;
        float a    = gng[o] * rsqrtf(fmaxf(var, 0.f) + EPSf);
        g_gn_a[t] = a;
        g_gn_b[t] = gnb[o] - mean * a;
    }
}

// ---------------- kernel 5: GN apply + ReLU ----------------
__global__ void k_gnapply(float* __restrict__ out) {
    int i = blockIdx.x * 256 + threadIdx.x;
    if (i >= (Bn*Cout*Ss) / 4) return;
    int cidx = i / (Ss / 4);
    float a = g_gn_a[cidx], bsh = g_gn_b[cidx];
    float4 v = reinterpret_cast<const float4*>(g_conv_out)[i];
    float4 r;
    r.x = fmaxf(fmaf(v.x, a, bsh), 0.f);
    r.y = fmaxf(fmaf(v.y, a, bsh), 0.f);
    r.z = fmaxf(fmaf(v.z, a, bsh), 0.f);
    r.w = fmaxf(fmaf(v.w, a, bsh), 0.f);
    reinterpret_cast<float4*>(out)[i] = r;
}

// ---------------- launch ----------------
extern "C" void kernel_launch(void* const* d_in, const int* in_sizes, int n_in,
                              void* d_out, int out_size) {
    const float* x   = (const float*)d_in[0];
    const float* ow  = (const float*)d_in[1];
    const float* ob  = (const float*)d_in[2];
    const float* bng = (const float*)d_in[3];
    const float* bnb = (const float*)d_in[4];
    const float* cw  = (const float*)d_in[5];
    const float* cb  = (const float*)d_in[6];
    const float* gng = (const float*)d_in[7];
    const float* gnb = (const float*)d_in[8];

    k_prepw<<<12, 256>>>(cw);
    k_offconv<<<NOB, 96>>>(x, ow, ob);
    k_bnred<<<12, 256>>>();
    k_bnfin<<<1, 32>>>(bng, bnb);
    k_sampconv<<<NSB, 256>>>(x, cb);
    k_gnred<<<64, 256>>>();
    k_gnfin<<<1, 128>>>(gng, gnb);
    k_gnapply<<<(Bn*Cout*Ss/4 + 255)/256, 256>>>((float*)d_out);
}